// round 14
// baseline (speedup 1.0000x reference)
#include <cuda_runtime.h>
#include <cuda_bf16.h>
#include <cstdint>

// Problem constants
#define Bb   8
#define Mm   512
#define Ll   1024
#define Hh   512
#define Kk   8
#define Dd   64
#define SKk  1536           // M + L
#define BKC  64             // B * K
#define SCALE 0.125f

// Scratch (device globals)
__device__ float gq[(size_t)BKC * Mm * Dd];      // [bk][s][d]
__device__ float gk[(size_t)BKC * SKk * Dd];     // [bk][s][d]
__device__ float gv[(size_t)BKC * Dd * SKk];     // [bk][d][s]  (transposed)
__device__ float gpe[Ll * Dd];                   // [j][d]
__device__ float g_ctx[(size_t)Bb * Mm * Hh];    // [B, M, K, D]
__device__ float gWr[4 * 512 * 512];             // tf32-rounded Wq,Wk,Wv,Wo

__device__ __forceinline__ float to_tf32(float x) {
    uint32_t r;
    asm("cvt.rna.tf32.f32 %0, %1;" : "=r"(r) : "f"(x));
    return __uint_as_float(r);
}
__device__ __forceinline__ uint32_t rna_u(float x) {
    uint32_t r;
    asm("cvt.rna.tf32.f32 %0, %1;" : "=r"(r) : "f"(x));
    return r;
}

#define MMA_TF32(c, a0, a1, a2, a3, b0, b1)                                   \
    asm volatile(                                                             \
        "mma.sync.aligned.m16n8k8.row.col.f32.tf32.tf32.f32 "                 \
        "{%0,%1,%2,%3},{%4,%5,%6,%7},{%8,%9},{%0,%1,%2,%3};"                  \
        : "+f"(c[0]), "+f"(c[1]), "+f"(c[2]), "+f"(c[3])                      \
        : "r"(a0), "r"(a1), "r"(a2), "r"(a3), "r"(b0), "r"(b1));

#define CP16(dst_sh, src)                                                     \
    asm volatile("cp.async.cg.shared.global [%0], [%1], 16;"                  \
                 :: "r"(dst_sh), "l"(src))
#define CP_COMMIT() asm volatile("cp.async.commit_group;")
#define CP_WAIT0()  asm volatile("cp.async.wait_group 0;" ::: "memory")

#define PJSTR 36
#define PJ_BUF (128 * PJSTR)
#define PROJ_SMEM_FLOATS (4 * PJ_BUF)

// ---------------------------------------------------------------------------
// Weight pre-round (rna idempotent -> consumers load raw, bit-identical).
// ---------------------------------------------------------------------------
__global__ void w_prep_kernel(const float* __restrict__ Wq,
                              const float* __restrict__ Wk,
                              const float* __restrict__ Wv,
                              const float* __restrict__ Wo) {
    int idx4 = (blockIdx.x * 256 + threadIdx.x) * 4;
    int plane = idx4 >> 18;
    int off   = idx4 & 262143;
    const float* W = (plane == 0) ? Wq : (plane == 1) ? Wk
                   : (plane == 2) ? Wv : Wo;
    float4 v = *(const float4*)(W + off);
    v.x = to_tf32(v.x); v.y = to_tf32(v.y);
    v.z = to_tf32(v.z); v.w = to_tf32(v.w);
    *(float4*)(gWr + idx4) = v;
}

// ---------------------------------------------------------------------------
// FUSED single-pass tf32 QKV projection + PE prep (unchanged from R13).
// ---------------------------------------------------------------------------
__global__ __launch_bounds__(256) void proj_fused_kernel(
        const float* __restrict__ query, const float* __restrict__ key,
        const float* __restrict__ value, const float* __restrict__ pe) {
    extern __shared__ float psm[];
    const int bid = blockIdx.x;

    if (bid >= 896) {
        int base = (bid - 896) * 4096 + threadIdx.x;
#pragma unroll
        for (int i = 0; i < 16; i++) {
            int idx = base + i * 256;
            int j = idx >> 6, d = idx & 63;
            gpe[idx] = to_tf32(pe[(size_t)d * Ll + j]);
        }
        return;
    }

    int sel, idx, S;
    const float *X, *W;
    if (bid < 128)      { sel = 0; idx = bid;       X = query; W = gWr;          S = Mm;  }
    else if (bid < 512) { sel = 1; idx = bid - 128; X = key;   W = gWr + 262144; S = SKk; }
    else                { sel = 2; idx = bid - 512; X = value; W = gWr + 524288; S = SKk; }

    const uint32_t base_sh = (uint32_t)__cvta_generic_to_shared(psm);
    const int tid  = threadIdx.x;
    const int lane = tid & 31;
    const int wid  = tid >> 5;
    const int warp_m = wid >> 1;
    const int warp_n = wid & 1;
    const int gid = lane >> 2;
    const int tig = lane & 3;
    const int row0 = (idx >> 2) * 128;
    const int col0 = (idx & 3) * 128;

    float c[2][8][4];
#pragma unroll
    for (int f = 0; f < 2; f++)
#pragma unroll
        for (int j = 0; j < 8; j++)
#pragma unroll
            for (int t = 0; t < 4; t++) c[f][j][t] = 0.f;

#pragma unroll
    for (int i = 0; i < 4; i++) {
        int f4 = tid + i * 256;
        int r  = f4 >> 3;
        int kq = (f4 & 7) << 2;
        CP16(base_sh + (uint32_t)(r * PJSTR + kq) * 4,
             X + (size_t)(row0 + r) * 512 + kq);
        CP16(base_sh + (uint32_t)(2 * PJ_BUF + r * PJSTR + kq) * 4,
             W + (size_t)(col0 + r) * 512 + kq);
    }
    CP_COMMIT();

    for (int kt = 0; kt < 16; kt++) {
        CP_WAIT0();
        __syncthreads();

        if (kt + 1 < 16) {
            int nb = (kt + 1) & 1;
            int k0 = (kt + 1) * 32;
#pragma unroll
            for (int i = 0; i < 4; i++) {
                int f4 = tid + i * 256;
                int r  = f4 >> 3;
                int kq = (f4 & 7) << 2;
                CP16(base_sh + (uint32_t)(nb * PJ_BUF + r * PJSTR + kq) * 4,
                     X + (size_t)(row0 + r) * 512 + k0 + kq);
                CP16(base_sh + (uint32_t)((2 + nb) * PJ_BUF + r * PJSTR + kq) * 4,
                     W + (size_t)(col0 + r) * 512 + k0 + kq);
            }
            CP_COMMIT();
        }

        const float* Xs = psm + (kt & 1) * PJ_BUF;
        const uint32_t* Wsu = (const uint32_t*)(psm + (2 + (kt & 1)) * PJ_BUF);

#pragma unroll
        for (int kk = 0; kk < 32; kk += 8) {
            uint32_t a[2][4];
#pragma unroll
            for (int f = 0; f < 2; f++) {
                int rbase = warp_m * 32 + f * 16 + gid;
#pragma unroll
                for (int rg = 0; rg < 4; rg++) {
                    int r    = rbase + ((rg & 1) << 3);
                    int kcol = kk + tig + ((rg >> 1) << 2);
                    a[f][rg] = rna_u(Xs[r * PJSTR + kcol]);
                }
            }
#pragma unroll
            for (int j = 0; j < 8; j++) {
                int cidx = warp_n * 64 + j * 8 + gid;
                uint32_t b0 = Wsu[cidx * PJSTR + kk + tig];
                uint32_t b1 = Wsu[cidx * PJSTR + kk + tig + 4];
#pragma unroll
                for (int f = 0; f < 2; f++)
                    MMA_TF32(c[f][j], a[f][0], a[f][1], a[f][2], a[f][3], b0, b1);
            }
        }
    }

    if (sel < 2) {
#pragma unroll
        for (int f = 0; f < 2; f++) {
            int rloc = warp_m * 32 + f * 16 + gid;
#pragma unroll
            for (int j = 0; j < 8; j++) {
                int cc = col0 + warp_n * 64 + j * 8 + 2 * tig;
#pragma unroll
                for (int h = 0; h < 2; h++) {
                    int r = row0 + rloc + h * 8;
                    int b = r / S, s = r - b * S;
                    int kh = cc >> 6, d = cc & 63;
                    int bk = b * Kk + kh;
                    float tx = to_tf32(c[f][j][h * 2]);
                    float ty = to_tf32(c[f][j][h * 2 + 1]);
                    if (sel == 0)
                        *(float2*)&gq[((size_t)bk * Mm + s) * Dd + d] = make_float2(tx, ty);
                    else
                        *(float2*)&gk[((size_t)bk * SKk + s) * Dd + d] = make_float2(tx, ty);
                }
            }
        }
    } else {
        __syncthreads();
        float* Ts = psm;
#pragma unroll
        for (int f = 0; f < 2; f++)
#pragma unroll
            for (int j = 0; j < 8; j++)
#pragma unroll
                for (int h = 0; h < 2; h++) {
                    int rl  = warp_m * 32 + f * 16 + gid + h * 8;
                    int ccl = warp_n * 64 + j * 8 + 2 * tig;
                    Ts[ccl * 132 + rl]       = to_tf32(c[f][j][h * 2]);
                    Ts[(ccl + 1) * 132 + rl] = to_tf32(c[f][j][h * 2 + 1]);
                }
        __syncthreads();
        int b     = row0 / SKk;
        int sbase = row0 - b * SKk;
        int ccl   = tid >> 1;
        int half  = (tid & 1) * 64;
        int cc = col0 + ccl;
        int kh = cc >> 6, d = cc & 63;
        float* dst = gv + ((size_t)(b * Kk + kh) * Dd + d) * SKk + sbase + half;
        const float* srcrow = Ts + ccl * 132 + half;
#pragma unroll
        for (int i = 0; i < 16; i++)
            *(float4*)(dst + i * 4) = *(const float4*)(srcrow + i * 4);
    }
}

// ---------------------------------------------------------------------------
// Single-pass tf32 output GEMM, 64x128 tiles (grid 256 -> fills chip,
// 55 KB smem -> multiple CTAs/SM). Wo pre-rounded in gWr[3].
// ---------------------------------------------------------------------------
#define OJ_XBUF (64 * PJSTR)    // 2304
#define OJ_WBUF (128 * PJSTR)   // 4608
#define OUT_SMEM_FLOATS (2 * OJ_XBUF + 2 * OJ_WBUF)   // 13824 = 55,296 B

__global__ __launch_bounds__(256) void proj_out_kernel(float* __restrict__ Yout) {
    extern __shared__ float psm[];
    const uint32_t base_sh = (uint32_t)__cvta_generic_to_shared(psm);
    const float* W = gWr + 786432;

    const int tid  = threadIdx.x;
    const int lane = tid & 31;
    const int wid  = tid >> 5;
    const int warp_m = wid & 3;          // 16-row blocks
    const int warp_n = wid >> 2;         // 0..1, 64-col halves
    const int gid = lane >> 2;
    const int tig = lane & 3;
    const int row0 = blockIdx.x * 64;
    const int col0 = blockIdx.y * 128;

    float c[8][4];
#pragma unroll
    for (int j = 0; j < 8; j++)
#pragma unroll
        for (int t = 0; t < 4; t++) c[j][t] = 0.f;

    // prologue: prefetch k-step 0 (X: 512 f4, W: 1024 f4)
#pragma unroll
    for (int i = 0; i < 2; i++) {
        int f4 = tid + i * 256;
        int r  = f4 >> 3;
        int kq = (f4 & 7) << 2;
        CP16(base_sh + (uint32_t)(r * PJSTR + kq) * 4,
             g_ctx + (size_t)(row0 + r) * 512 + kq);
    }
#pragma unroll
    for (int i = 0; i < 4; i++) {
        int f4 = tid + i * 256;
        int r  = f4 >> 3;
        int kq = (f4 & 7) << 2;
        CP16(base_sh + (uint32_t)(2 * OJ_XBUF + r * PJSTR + kq) * 4,
             W + (size_t)(col0 + r) * 512 + kq);
    }
    CP_COMMIT();

    for (int kt = 0; kt < 16; kt++) {
        CP_WAIT0();
        __syncthreads();

        if (kt + 1 < 16) {
            int nb = (kt + 1) & 1;
            int k0 = (kt + 1) * 32;
#pragma unroll
            for (int i = 0; i < 2; i++) {
                int f4 = tid + i * 256;
                int r  = f4 >> 3;
                int kq = (f4 & 7) << 2;
                CP16(base_sh + (uint32_t)(nb * OJ_XBUF + r * PJSTR + kq) * 4,
                     g_ctx + (size_t)(row0 + r) * 512 + k0 + kq);
            }
#pragma unroll
            for (int i = 0; i < 4; i++) {
                int f4 = tid + i * 256;
                int r  = f4 >> 3;
                int kq = (f4 & 7) << 2;
                CP16(base_sh + (uint32_t)(2 * OJ_XBUF + nb * OJ_WBUF + r * PJSTR + kq) * 4,
                     W + (size_t)(col0 + r) * 512 + k0 + kq);
            }
            CP_COMMIT();
        }

        const float* Xs = psm + (kt & 1) * OJ_XBUF;
        const uint32_t* Wsu = (const uint32_t*)(psm + 2 * OJ_XBUF + (kt & 1) * OJ_WBUF);

#pragma unroll
        for (int kk = 0; kk < 32; kk += 8) {
            uint32_t a[4];
            int rbase = warp_m * 16 + gid;
#pragma unroll
            for (int rg = 0; rg < 4; rg++) {
                int r    = rbase + ((rg & 1) << 3);
                int kcol = kk + tig + ((rg >> 1) << 2);
                a[rg] = rna_u(Xs[r * PJSTR + kcol]);
            }
#pragma unroll
            for (int j = 0; j < 8; j++) {
                int cidx = warp_n * 64 + j * 8 + gid;
                uint32_t b0 = Wsu[cidx * PJSTR + kk + tig];
                uint32_t b1 = Wsu[cidx * PJSTR + kk + tig + 4];
                MMA_TF32(c[j], a[0], a[1], a[2], a[3], b0, b1);
            }
        }
    }

#pragma unroll
    for (int j = 0; j < 8; j++) {
        int cc = col0 + warp_n * 64 + j * 8 + 2 * tig;
#pragma unroll
        for (int h = 0; h < 2; h++) {
            int r = row0 + warp_m * 16 + gid + h * 8;
            *(float2*)(Yout + (size_t)r * 512 + cc) =
                make_float2(c[j][h * 2], c[j][h * 2 + 1]);
        }
    }
}

// ---------------------------------------------------------------------------
// Single-pass tf32 MMA banded attention — 512 threads / 16 warps.
// Warp (mb = wid&3, q4 = wid>>2):
//   score: QK band tiles {3,3,2,2} of the 10 in [2mb, 2mb+9] + 2 PE tiles
//          (cols q4*16, q4*16+8)
//   AV:    n-quarter cols q4*16..+15, 10 band k-blocks -> oacc[2][4]
// Softmax: 8 threads/row. cp.async pipeline as R10-13.
// ---------------------------------------------------------------------------
#define QSTR 68
#define KSTR 68
#define VSTR 132
#define PSTR2 132
#define OFF_Q    0
#define OFF_K    (OFF_Q + 64 * QSTR)
#define OFF_PE   (OFF_K + 128 * KSTR)
#define OFF_V    (OFF_PE + 64 * QSTR)
#define OFF_P    (OFF_V + 2 * 64 * VSTR)
#define OFF_SREL (OFF_P + 64 * PSTR2)
#define OFF_SPE  (OFF_SREL + 64 * QSTR)
#define OFF_CORR (OFF_SPE + 64 * QSTR)
#define OFF_LINV (OFF_CORR + 64)
#define ATTN_SMEM_FLOATS (OFF_LINV + 64)

__global__ __launch_bounds__(512) void attn_mma_kernel(
        const float* __restrict__ span_val) {
    extern __shared__ float sm[];
    float* Qs    = sm + OFF_Q;
    float* Ks    = sm + OFF_K;
    float* PEs   = sm + OFF_PE;
    float* Vbase = sm + OFF_V;
    float* Ps    = sm + OFF_P;
    float* Srel  = sm + OFF_SREL;
    float* Spe   = sm + OFF_SPE;
    float* corr_s = sm + OFF_CORR;
    float* linv_s = sm + OFF_LINV;

    const uint32_t* Qu  = (const uint32_t*)Qs;
    const uint32_t* Ku  = (const uint32_t*)Ks;
    const uint32_t* PEu = (const uint32_t*)PEs;
    const uint32_t* Pu  = (const uint32_t*)Ps;

    const int tid  = threadIdx.x;
    const int lane = tid & 31;
    const int wid  = tid >> 5;           // 0..15
    const int gid  = lane >> 2;
    const int tig  = lane & 3;
    const int bk   = blockIdx.y;
    const int i0   = blockIdx.x * 64;
    const int kh   = bk & 7;

    const int mb  = wid & 3;
    const int q4  = wid >> 2;            // 0..3
    const int m0  = mb * 16;
    const int npb = q4 * 16;             // AV/PE n-base
    const int qk_cnt = (q4 < 2) ? 3 : 2;
    const int qk_off = (q4 < 2) ? q4 * 3 : 6 + (q4 - 2) * 2;
    const int jt0 = 2 * mb + qk_off;

    const int srow = tid >> 3;           // 8 threads per row
    const int tg8  = tid & 7;
    const int tbase = tg8 * 8;
    const float spanL = span_val[kh] * 1024.f;

    const float* gkp_base = gk + ((size_t)bk * SKk + i0) * Dd;
    const float* gvp_base = gv + (size_t)bk * Dd * SKk + i0;

    const int kr  = tid >> 4, kc4 = (tid & 15) << 2;   // 32 rows per iter
    const int vd  = tid >> 5, vc4 = (tid & 31) << 2;   // 16 d-rows per iter

    const uint32_t Ksh  = (uint32_t)__cvta_generic_to_shared(Ks);
    const uint32_t PEsh = (uint32_t)__cvta_generic_to_shared(PEs);
    const uint32_t Vsh  = (uint32_t)__cvta_generic_to_shared(Vbase);

    // ---- prologue
    {
        const float* gqp = gq + ((size_t)bk * Mm + i0) * Dd;
#pragma unroll
        for (int it = 0; it < 2; it++) {
            int idx = tid + it * 512;
            int r = idx >> 4, c4 = (idx & 15) << 2;
            float4 v = *(const float4*)(gqp + (size_t)r * Dd + c4);
            v.x *= SCALE; v.y *= SCALE; v.z *= SCALE; v.w *= SCALE;
            *(float4*)&Qs[r * QSTR + c4] = v;
        }
#pragma unroll
        for (int it = 0; it < 17; it++) {
            int idx = tid + it * 512;
            if (idx < 64 * PSTR2) Ps[idx] = 0.f;
        }
#pragma unroll
        for (int it = 0; it < 4; it++) {
            int r = kr + it * 32;
            CP16(Ksh + (uint32_t)(r * KSTR + kc4) * 4,
                 gkp_base + (size_t)r * Dd + kc4);
        }
#pragma unroll
        for (int it = 0; it < 2; it++) {
            int r = kr + it * 32;
            CP16(PEsh + (uint32_t)(r * QSTR + kc4) * 4,
                 gpe + (size_t)r * Dd + kc4);
        }
#pragma unroll
        for (int it = 0; it < 4; it++) {
            int d = vd + it * 16;
            CP16(Vsh + (uint32_t)(d * VSTR + vc4) * 4,
                 gvp_base + (size_t)d * SKk + vc4);
        }
        CP_COMMIT();
    }

    float oacc[2][4];
#pragma unroll
    for (int j = 0; j < 2; j++)
#pragma unroll
        for (int t = 0; t < 4; t++) oacc[j][t] = 0.f;

    float m_run = -1e30f, l_run = 0.f;

    for (int cidx = 0; cidx < 16; cidx++) {
        const int jc = cidx * 64;
        const uint32_t* Vu = (const uint32_t*)(Vbase + (cidx & 1) * 64 * VSTR);

        CP_WAIT0();
        __syncthreads();                 // S1

        if (cidx + 1 < 16) {
            uint32_t vdst = Vsh + (uint32_t)(((cidx + 1) & 1) * 64 * VSTR) * 4;
            const float* vsrc = gvp_base + (cidx + 1) * 64;
#pragma unroll
            for (int it = 0; it < 4; it++) {
                int d = vd + it * 16;
                CP16(vdst + (uint32_t)(d * VSTR + vc4) * 4,
                     vsrc + (size_t)d * SKk + vc4);
            }
            CP_COMMIT();
        }

        // ---- score MMAs
        float sacc[3][4], pacc[2][4];
#pragma unroll
        for (int j = 0; j < 3; j++)
#pragma unroll
            for (int t = 0; t < 4; t++) sacc[j][t] = 0.f;
#pragma unroll
        for (int j = 0; j < 2; j++)
#pragma unroll
            for (int t = 0; t < 4; t++) pacc[j][t] = 0.f;

#pragma unroll
        for (int k0 = 0; k0 < 64; k0 += 8) {
            int ar = (m0 + gid) * QSTR + k0 + tig;
            uint32_t a0 = Qu[ar];
            uint32_t a1 = Qu[ar + 8 * QSTR];
            uint32_t a2 = Qu[ar + 4];
            uint32_t a3 = Qu[ar + 8 * QSTR + 4];
#pragma unroll
            for (int jj = 0; jj < 3; jj++) {
                if (jj < qk_cnt) {
                    int br = ((jt0 + jj) * 8 + gid) * KSTR + k0 + tig;
                    MMA_TF32(sacc[jj], a0, a1, a2, a3, Ku[br], Ku[br + 4]);
                }
            }
#pragma unroll
            for (int j = 0; j < 2; j++) {
                int br = (npb + 8 * j + gid) * QSTR + k0 + tig;
                MMA_TF32(pacc[j], a0, a1, a2, a3, PEu[br], PEu[br + 4]);
            }
        }

        // scatter QK band -> de-skewed Srel[i][col-row]
#pragma unroll
        for (int jj = 0; jj < 3; jj++) {
            if (jj < qk_cnt) {
                int col = (jt0 + jj) * 8 + 2 * tig;
                int r0 = m0 + gid, r1 = r0 + 8;
                int t00 = col - r0, t10 = col - r1;
                if ((unsigned)t00 < 64u)       Srel[r0 * QSTR + t00]     = sacc[jj][0];
                if ((unsigned)(t00 + 1) < 64u) Srel[r0 * QSTR + t00 + 1] = sacc[jj][1];
                if ((unsigned)t10 < 64u)       Srel[r1 * QSTR + t10]     = sacc[jj][2];
                if ((unsigned)(t10 + 1) < 64u) Srel[r1 * QSTR + t10 + 1] = sacc[jj][3];
            }
        }
#pragma unroll
        for (int j = 0; j < 2; j++) {
            int col = npb + 8 * j + 2 * tig;
            Spe[(m0 + gid) * QSTR + col]     = pacc[j][0];
            Spe[(m0 + gid) * QSTR + col + 1] = pacc[j][1];
            Spe[(m0 + gid + 8) * QSTR + col]     = pacc[j][2];
            Spe[(m0 + gid + 8) * QSTR + col + 1] = pacc[j][3];
        }
        __syncthreads();                 // S2

        if (cidx + 1 < 16) {
            const float* ksrc = gkp_base + (size_t)(cidx + 1) * 64 * Dd;
            const float* psrc = gpe + (size_t)(cidx + 1) * 64 * Dd;
#pragma unroll
            for (int it = 0; it < 4; it++) {
                int r = kr + it * 32;
                CP16(Ksh + (uint32_t)(r * KSTR + kc4) * 4,
                     ksrc + (size_t)r * Dd + kc4);
            }
#pragma unroll
            for (int it = 0; it < 2; it++) {
                int r = kr + it * 32;
                CP16(PEsh + (uint32_t)(r * QSTR + kc4) * 4,
                     psrc + (size_t)r * Dd + kc4);
            }
            CP_COMMIT();
        }

        // ---- online softmax (8 threads/row, 8 elems each)
        {
            float s[8];
            float mloc = -1e30f;
#pragma unroll
            for (int e = 0; e < 8; e++) {
                s[e] = Srel[srow * QSTR + tbase + e] + Spe[srow * QSTR + tbase + e];
                mloc = fmaxf(mloc, s[e]);
            }
            mloc = fmaxf(mloc, __shfl_xor_sync(0xFFFFFFFFu, mloc, 1));
            mloc = fmaxf(mloc, __shfl_xor_sync(0xFFFFFFFFu, mloc, 2));
            mloc = fmaxf(mloc, __shfl_xor_sync(0xFFFFFFFFu, mloc, 4));
            float m_new = fmaxf(m_run, mloc);
            float corr  = __expf(m_run - m_new);
            l_run *= corr;
            float p[8], psum = 0.f;
#pragma unroll
            for (int e = 0; e < 8; e++) { p[e] = __expf(s[e] - m_new); psum += p[e]; }
            psum += __shfl_xor_sync(0xFFFFFFFFu, psum, 1);
            psum += __shfl_xor_sync(0xFFFFFFFFu, psum, 2);
            psum += __shfl_xor_sync(0xFFFFFFFFu, psum, 4);
            l_run += psum;
            m_run = m_new;
            if (tg8 == 0) corr_s[srow] = corr;

#pragma unroll
            for (int e = 0; e < 8; e++) {
                int t = tbase + e;
                float jj = (float)(jc + t);
                float mk = fminf(1.f, fmaxf(0.f, (jj - 1023.f + spanL) * (1.f / 32.f) + 1.f));
                Ps[srow * PSTR2 + srow + t] = to_tf32(p[e] * mk);
            }
        }
        __syncthreads();                 // S3

        // ---- AV: oacc = oacc*corr + P @ V^T  (n-quarter, band k-blocks)
        {
            float cA = corr_s[m0 + gid], cB = corr_s[m0 + gid + 8];
#pragma unroll
            for (int j = 0; j < 2; j++) {
                oacc[j][0] *= cA; oacc[j][1] *= cA;
                oacc[j][2] *= cB; oacc[j][3] *= cB;
            }
#pragma unroll
            for (int kk = 0; kk < 10; kk++) {
                int k0 = (2 * mb + kk) * 8;
                int ar = (m0 + gid) * PSTR2 + k0 + tig;
                uint32_t a0 = Pu[ar];
                uint32_t a1 = Pu[ar + 8 * PSTR2];
                uint32_t a2 = Pu[ar + 4];
                uint32_t a3 = Pu[ar + 8 * PSTR2 + 4];
#pragma unroll
                for (int j = 0; j < 2; j++) {
                    int br = (npb + 8 * j + gid) * VSTR + k0 + tig;
                    MMA_TF32(oacc[j], a0, a1, a2, a3, Vu[br], Vu[br + 4]);
                }
            }
        }
    }

    __syncthreads();
    if (tg8 == 0) linv_s[srow] = 1.f / l_run;
    __syncthreads();

    // epilogue: g_ctx[b][i0+row][kh][d]
    {
        float lA = linv_s[m0 + gid], lB = linv_s[m0 + gid + 8];
        int b = bk >> 3;
        int r0 = i0 + m0 + gid;
#pragma unroll
        for (int j = 0; j < 2; j++) {
            int col = npb + 8 * j + 2 * tig;
            float* p0 = g_ctx + ((size_t)(b * Mm + r0) * Kk + kh) * Dd + col;
            float* p1 = g_ctx + ((size_t)(b * Mm + r0 + 8) * Kk + kh) * Dd + col;
            *(float2*)p0 = make_float2(oacc[j][0] * lA, oacc[j][1] * lA);
            *(float2*)p1 = make_float2(oacc[j][2] * lB, oacc[j][3] * lB);
        }
    }
}

// ---------------------------------------------------------------------------
extern "C" void kernel_launch(void* const* d_in, const int* in_sizes, int n_in,
                              void* d_out, int out_size) {
    const float* query = (const float*)d_in[0];
    const float* key   = (const float*)d_in[1];
    const float* value = (const float*)d_in[2];
    const float* pe    = (const float*)d_in[3];
    const float* Wq    = (const float*)d_in[4];
    const float* Wk    = (const float*)d_in[5];
    const float* Wv    = (const float*)d_in[6];
    const float* Wo    = (const float*)d_in[7];
    const float* span  = (const float*)d_in[8];
    float* out = (float*)d_out;

    cudaFuncSetAttribute(attn_mma_kernel,
                         cudaFuncAttributeMaxDynamicSharedMemorySize,
                         ATTN_SMEM_FLOATS * (int)sizeof(float));
    cudaFuncSetAttribute(proj_fused_kernel,
                         cudaFuncAttributeMaxDynamicSharedMemorySize,
                         PROJ_SMEM_FLOATS * (int)sizeof(float));
    cudaFuncSetAttribute(proj_out_kernel,
                         cudaFuncAttributeMaxDynamicSharedMemorySize,
                         OUT_SMEM_FLOATS * (int)sizeof(float));

    w_prep_kernel<<<1024, 256>>>(Wq, Wk, Wv, Wo);

    proj_fused_kernel<<<912, 256, PROJ_SMEM_FLOATS * (int)sizeof(float)>>>(
        query, key, value, pe);

    attn_mma_kernel<<<dim3(Mm / 64, BKC), 512,
                      ATTN_SMEM_FLOATS * (int)sizeof(float)>>>(span);

    proj_out_kernel<<<dim3(Bb * Mm / 64, 4), 256,
                      OUT_SMEM_FLOATS * (int)sizeof(float)>>>(out);
}

// round 15
// speedup vs baseline: 1.0606x; 1.0606x over previous
#include <cuda_runtime.h>
#include <cuda_bf16.h>
#include <cstdint>

// Problem constants
#define Bb   8
#define Mm   512
#define Ll   1024
#define Hh   512
#define Kk   8
#define Dd   64
#define SKk  1536           // M + L
#define BKC  64             // B * K
#define SCALE 0.125f

// Scratch (device globals)
__device__ float gq[(size_t)BKC * Mm * Dd];      // [bk][s][d]
__device__ float gk[(size_t)BKC * SKk * Dd];     // [bk][s][d]
__device__ float gv[(size_t)BKC * Dd * SKk];     // [bk][d][s]  (transposed)
__device__ float gpe[Ll * Dd];                   // [j][d]
__device__ float g_ctx[(size_t)Bb * Mm * Hh];    // [B, M, K, D]
__device__ float gWr[4 * 512 * 512];             // tf32-rounded Wq,Wk,Wv,Wo

__device__ __forceinline__ float to_tf32(float x) {
    uint32_t r;
    asm("cvt.rna.tf32.f32 %0, %1;" : "=r"(r) : "f"(x));
    return __uint_as_float(r);
}
__device__ __forceinline__ uint32_t rna_u(float x) {
    uint32_t r;
    asm("cvt.rna.tf32.f32 %0, %1;" : "=r"(r) : "f"(x));
    return r;
}

#define MMA_TF32(c, a0, a1, a2, a3, b0, b1)                                   \
    asm volatile(                                                             \
        "mma.sync.aligned.m16n8k8.row.col.f32.tf32.tf32.f32 "                 \
        "{%0,%1,%2,%3},{%4,%5,%6,%7},{%8,%9},{%0,%1,%2,%3};"                  \
        : "+f"(c[0]), "+f"(c[1]), "+f"(c[2]), "+f"(c[3])                      \
        : "r"(a0), "r"(a1), "r"(a2), "r"(a3), "r"(b0), "r"(b1));

#define CP16(dst_sh, src)                                                     \
    asm volatile("cp.async.cg.shared.global [%0], [%1], 16;"                  \
                 :: "r"(dst_sh), "l"(src))
#define CP_COMMIT() asm volatile("cp.async.commit_group;")
#define CP_WAIT0()  asm volatile("cp.async.wait_group 0;" ::: "memory")

#define PJSTR 36
#define PJ_BUF (128 * PJSTR)
#define PROJ_SMEM_FLOATS (4 * PJ_BUF)

// ---------------------------------------------------------------------------
// Weight pre-round (rna idempotent -> consumers load raw, bit-identical).
// ---------------------------------------------------------------------------
__global__ void w_prep_kernel(const float* __restrict__ Wq,
                              const float* __restrict__ Wk,
                              const float* __restrict__ Wv,
                              const float* __restrict__ Wo) {
    int idx4 = (blockIdx.x * 256 + threadIdx.x) * 4;
    int plane = idx4 >> 18;
    int off   = idx4 & 262143;
    const float* W = (plane == 0) ? Wq : (plane == 1) ? Wk
                   : (plane == 2) ? Wv : Wo;
    float4 v = *(const float4*)(W + off);
    v.x = to_tf32(v.x); v.y = to_tf32(v.y);
    v.z = to_tf32(v.z); v.w = to_tf32(v.w);
    *(float4*)(gWr + idx4) = v;
}

// ---------------------------------------------------------------------------
// FUSED single-pass tf32 QKV projection + PE prep (R13).
// ---------------------------------------------------------------------------
__global__ __launch_bounds__(256) void proj_fused_kernel(
        const float* __restrict__ query, const float* __restrict__ key,
        const float* __restrict__ value, const float* __restrict__ pe) {
    extern __shared__ float psm[];
    const int bid = blockIdx.x;

    if (bid >= 896) {
        int base = (bid - 896) * 4096 + threadIdx.x;
#pragma unroll
        for (int i = 0; i < 16; i++) {
            int idx = base + i * 256;
            int j = idx >> 6, d = idx & 63;
            gpe[idx] = to_tf32(pe[(size_t)d * Ll + j]);
        }
        return;
    }

    int sel, idx, S;
    const float *X, *W;
    if (bid < 128)      { sel = 0; idx = bid;       X = query; W = gWr;          S = Mm;  }
    else if (bid < 512) { sel = 1; idx = bid - 128; X = key;   W = gWr + 262144; S = SKk; }
    else                { sel = 2; idx = bid - 512; X = value; W = gWr + 524288; S = SKk; }

    const uint32_t base_sh = (uint32_t)__cvta_generic_to_shared(psm);
    const int tid  = threadIdx.x;
    const int lane = tid & 31;
    const int wid  = tid >> 5;
    const int warp_m = wid >> 1;
    const int warp_n = wid & 1;
    const int gid = lane >> 2;
    const int tig = lane & 3;
    const int row0 = (idx >> 2) * 128;
    const int col0 = (idx & 3) * 128;

    float c[2][8][4];
#pragma unroll
    for (int f = 0; f < 2; f++)
#pragma unroll
        for (int j = 0; j < 8; j++)
#pragma unroll
            for (int t = 0; t < 4; t++) c[f][j][t] = 0.f;

#pragma unroll
    for (int i = 0; i < 4; i++) {
        int f4 = tid + i * 256;
        int r  = f4 >> 3;
        int kq = (f4 & 7) << 2;
        CP16(base_sh + (uint32_t)(r * PJSTR + kq) * 4,
             X + (size_t)(row0 + r) * 512 + kq);
        CP16(base_sh + (uint32_t)(2 * PJ_BUF + r * PJSTR + kq) * 4,
             W + (size_t)(col0 + r) * 512 + kq);
    }
    CP_COMMIT();

    for (int kt = 0; kt < 16; kt++) {
        CP_WAIT0();
        __syncthreads();

        if (kt + 1 < 16) {
            int nb = (kt + 1) & 1;
            int k0 = (kt + 1) * 32;
#pragma unroll
            for (int i = 0; i < 4; i++) {
                int f4 = tid + i * 256;
                int r  = f4 >> 3;
                int kq = (f4 & 7) << 2;
                CP16(base_sh + (uint32_t)(nb * PJ_BUF + r * PJSTR + kq) * 4,
                     X + (size_t)(row0 + r) * 512 + k0 + kq);
                CP16(base_sh + (uint32_t)((2 + nb) * PJ_BUF + r * PJSTR + kq) * 4,
                     W + (size_t)(col0 + r) * 512 + k0 + kq);
            }
            CP_COMMIT();
        }

        const float* Xs = psm + (kt & 1) * PJ_BUF;
        const uint32_t* Wsu = (const uint32_t*)(psm + (2 + (kt & 1)) * PJ_BUF);

#pragma unroll
        for (int kk = 0; kk < 32; kk += 8) {
            uint32_t a[2][4];
#pragma unroll
            for (int f = 0; f < 2; f++) {
                int rbase = warp_m * 32 + f * 16 + gid;
#pragma unroll
                for (int rg = 0; rg < 4; rg++) {
                    int r    = rbase + ((rg & 1) << 3);
                    int kcol = kk + tig + ((rg >> 1) << 2);
                    a[f][rg] = rna_u(Xs[r * PJSTR + kcol]);
                }
            }
#pragma unroll
            for (int j = 0; j < 8; j++) {
                int cidx = warp_n * 64 + j * 8 + gid;
                uint32_t b0 = Wsu[cidx * PJSTR + kk + tig];
                uint32_t b1 = Wsu[cidx * PJSTR + kk + tig + 4];
#pragma unroll
                for (int f = 0; f < 2; f++)
                    MMA_TF32(c[f][j], a[f][0], a[f][1], a[f][2], a[f][3], b0, b1);
            }
        }
    }

    if (sel < 2) {
#pragma unroll
        for (int f = 0; f < 2; f++) {
            int rloc = warp_m * 32 + f * 16 + gid;
#pragma unroll
            for (int j = 0; j < 8; j++) {
                int cc = col0 + warp_n * 64 + j * 8 + 2 * tig;
#pragma unroll
                for (int h = 0; h < 2; h++) {
                    int r = row0 + rloc + h * 8;
                    int b = r / S, s = r - b * S;
                    int kh = cc >> 6, d = cc & 63;
                    int bk = b * Kk + kh;
                    float tx = to_tf32(c[f][j][h * 2]);
                    float ty = to_tf32(c[f][j][h * 2 + 1]);
                    if (sel == 0)
                        *(float2*)&gq[((size_t)bk * Mm + s) * Dd + d] = make_float2(tx, ty);
                    else
                        *(float2*)&gk[((size_t)bk * SKk + s) * Dd + d] = make_float2(tx, ty);
                }
            }
        }
    } else {
        __syncthreads();
        float* Ts = psm;
#pragma unroll
        for (int f = 0; f < 2; f++)
#pragma unroll
            for (int j = 0; j < 8; j++)
#pragma unroll
                for (int h = 0; h < 2; h++) {
                    int rl  = warp_m * 32 + f * 16 + gid + h * 8;
                    int ccl = warp_n * 64 + j * 8 + 2 * tig;
                    Ts[ccl * 132 + rl]       = to_tf32(c[f][j][h * 2]);
                    Ts[(ccl + 1) * 132 + rl] = to_tf32(c[f][j][h * 2 + 1]);
                }
        __syncthreads();
        int b     = row0 / SKk;
        int sbase = row0 - b * SKk;
        int ccl   = tid >> 1;
        int half  = (tid & 1) * 64;
        int cc = col0 + ccl;
        int kh = cc >> 6, d = cc & 63;
        float* dst = gv + ((size_t)(b * Kk + kh) * Dd + d) * SKk + sbase + half;
        const float* srcrow = Ts + ccl * 132 + half;
#pragma unroll
        for (int i = 0; i < 16; i++)
            *(float4*)(dst + i * 4) = *(const float4*)(srcrow + i * 4);
    }
}

// ---------------------------------------------------------------------------
// Single-pass tf32 output GEMM, 64x128 tiles (R14 version — kept).
// ---------------------------------------------------------------------------
#define OJ_XBUF (64 * PJSTR)
#define OJ_WBUF (128 * PJSTR)
#define OUT_SMEM_FLOATS (2 * OJ_XBUF + 2 * OJ_WBUF)

__global__ __launch_bounds__(256) void proj_out_kernel(float* __restrict__ Yout) {
    extern __shared__ float psm[];
    const uint32_t base_sh = (uint32_t)__cvta_generic_to_shared(psm);
    const float* W = gWr + 786432;

    const int tid  = threadIdx.x;
    const int lane = tid & 31;
    const int wid  = tid >> 5;
    const int warp_m = wid & 3;
    const int warp_n = wid >> 2;
    const int gid = lane >> 2;
    const int tig = lane & 3;
    const int row0 = blockIdx.x * 64;
    const int col0 = blockIdx.y * 128;

    float c[8][4];
#pragma unroll
    for (int j = 0; j < 8; j++)
#pragma unroll
        for (int t = 0; t < 4; t++) c[j][t] = 0.f;

#pragma unroll
    for (int i = 0; i < 2; i++) {
        int f4 = tid + i * 256;
        int r  = f4 >> 3;
        int kq = (f4 & 7) << 2;
        CP16(base_sh + (uint32_t)(r * PJSTR + kq) * 4,
             g_ctx + (size_t)(row0 + r) * 512 + kq);
    }
#pragma unroll
    for (int i = 0; i < 4; i++) {
        int f4 = tid + i * 256;
        int r  = f4 >> 3;
        int kq = (f4 & 7) << 2;
        CP16(base_sh + (uint32_t)(2 * OJ_XBUF + r * PJSTR + kq) * 4,
             W + (size_t)(col0 + r) * 512 + kq);
    }
    CP_COMMIT();

    for (int kt = 0; kt < 16; kt++) {
        CP_WAIT0();
        __syncthreads();

        if (kt + 1 < 16) {
            int nb = (kt + 1) & 1;
            int k0 = (kt + 1) * 32;
#pragma unroll
            for (int i = 0; i < 2; i++) {
                int f4 = tid + i * 256;
                int r  = f4 >> 3;
                int kq = (f4 & 7) << 2;
                CP16(base_sh + (uint32_t)(nb * OJ_XBUF + r * PJSTR + kq) * 4,
                     g_ctx + (size_t)(row0 + r) * 512 + k0 + kq);
            }
#pragma unroll
            for (int i = 0; i < 4; i++) {
                int f4 = tid + i * 256;
                int r  = f4 >> 3;
                int kq = (f4 & 7) << 2;
                CP16(base_sh + (uint32_t)(2 * OJ_XBUF + nb * OJ_WBUF + r * PJSTR + kq) * 4,
                     W + (size_t)(col0 + r) * 512 + k0 + kq);
            }
            CP_COMMIT();
        }

        const float* Xs = psm + (kt & 1) * OJ_XBUF;
        const uint32_t* Wsu = (const uint32_t*)(psm + 2 * OJ_XBUF + (kt & 1) * OJ_WBUF);

#pragma unroll
        for (int kk = 0; kk < 32; kk += 8) {
            uint32_t a[4];
            int rbase = warp_m * 16 + gid;
#pragma unroll
            for (int rg = 0; rg < 4; rg++) {
                int r    = rbase + ((rg & 1) << 3);
                int kcol = kk + tig + ((rg >> 1) << 2);
                a[rg] = rna_u(Xs[r * PJSTR + kcol]);
            }
#pragma unroll
            for (int j = 0; j < 8; j++) {
                int cidx = warp_n * 64 + j * 8 + gid;
                uint32_t b0 = Wsu[cidx * PJSTR + kk + tig];
                uint32_t b1 = Wsu[cidx * PJSTR + kk + tig + 4];
                MMA_TF32(c[j], a[0], a[1], a[2], a[3], b0, b1);
            }
        }
    }

#pragma unroll
    for (int j = 0; j < 8; j++) {
        int cc = col0 + warp_n * 64 + j * 8 + 2 * tig;
#pragma unroll
        for (int h = 0; h < 2; h++) {
            int r = row0 + warp_m * 16 + gid + h * 8;
            *(float2*)(Yout + (size_t)r * 512 + cc) =
                make_float2(c[j][h * 2], c[j][h * 2 + 1]);
        }
    }
}

// ---------------------------------------------------------------------------
// Single-pass tf32 MMA banded attention — R13 version (256 thr, 8 warps,
// 5+4 tile ownership, cp.async pipelined). Best measured configuration.
// ---------------------------------------------------------------------------
#define QSTR 68
#define KSTR 68
#define VSTR 132
#define PSTR2 132
#define OFF_Q    0
#define OFF_K    (OFF_Q + 64 * QSTR)
#define OFF_PE   (OFF_K + 128 * KSTR)
#define OFF_V    (OFF_PE + 64 * QSTR)
#define OFF_P    (OFF_V + 2 * 64 * VSTR)
#define OFF_SREL (OFF_P + 64 * PSTR2)
#define OFF_SPE  (OFF_SREL + 64 * QSTR)
#define OFF_CORR (OFF_SPE + 64 * QSTR)
#define OFF_LINV (OFF_CORR + 64)
#define ATTN_SMEM_FLOATS (OFF_LINV + 64)

__global__ __launch_bounds__(256) void attn_mma_kernel(
        const float* __restrict__ span_val) {
    extern __shared__ float sm[];
    float* Qs    = sm + OFF_Q;
    float* Ks    = sm + OFF_K;
    float* PEs   = sm + OFF_PE;
    float* Vbase = sm + OFF_V;
    float* Ps    = sm + OFF_P;
    float* Srel  = sm + OFF_SREL;
    float* Spe   = sm + OFF_SPE;
    float* corr_s = sm + OFF_CORR;
    float* linv_s = sm + OFF_LINV;

    const uint32_t* Qu  = (const uint32_t*)Qs;
    const uint32_t* Ku  = (const uint32_t*)Ks;
    const uint32_t* PEu = (const uint32_t*)PEs;
    const uint32_t* Pu  = (const uint32_t*)Ps;

    const int tid  = threadIdx.x;
    const int lane = tid & 31;
    const int wid  = tid >> 5;
    const int gid  = lane >> 2;
    const int tig  = lane & 3;
    const int bk   = blockIdx.y;
    const int i0   = blockIdx.x * 64;
    const int kh   = bk & 7;

    const int mb  = wid & 3;
    const int m0  = mb * 16;
    const int np0 = (wid >> 2) * 32;
    const int jt0 = 2 * mb + 5 * (wid >> 2);

    const int srow = tid >> 2;
    const int tg4  = tid & 3;
    const int tbase = tg4 * 16;
    const float spanL = span_val[kh] * 1024.f;

    const float* gkp_base = gk + ((size_t)bk * SKk + i0) * Dd;
    const float* gvp_base = gv + (size_t)bk * Dd * SKk + i0;

    const int kr  = tid >> 4, kc4 = (tid & 15) << 2;
    const int vd  = tid >> 5, vc4 = (tid & 31) << 2;

    const uint32_t Ksh  = (uint32_t)__cvta_generic_to_shared(Ks);
    const uint32_t PEsh = (uint32_t)__cvta_generic_to_shared(PEs);
    const uint32_t Vsh  = (uint32_t)__cvta_generic_to_shared(Vbase);

    {
        const float* gqp = gq + ((size_t)bk * Mm + i0) * Dd;
#pragma unroll
        for (int it = 0; it < 4; it++) {
            int idx = tid + it * 256;
            int r = idx >> 4, c4 = (idx & 15) << 2;
            float4 v = *(const float4*)(gqp + (size_t)r * Dd + c4);
            v.x *= SCALE; v.y *= SCALE; v.z *= SCALE; v.w *= SCALE;
            *(float4*)&Qs[r * QSTR + c4] = v;
        }
#pragma unroll
        for (int it = 0; it < 33; it++) {
            int idx = tid + it * 256;
            if (idx < 64 * PSTR2) Ps[idx] = 0.f;
        }
#pragma unroll
        for (int it = 0; it < 8; it++) {
            int r = kr + it * 16;
            CP16(Ksh + (uint32_t)(r * KSTR + kc4) * 4,
                 gkp_base + (size_t)r * Dd + kc4);
        }
#pragma unroll
        for (int it = 0; it < 4; it++) {
            int r = kr + it * 16;
            CP16(PEsh + (uint32_t)(r * QSTR + kc4) * 4,
                 gpe + (size_t)r * Dd + kc4);
        }
#pragma unroll
        for (int it = 0; it < 8; it++) {
            int d = vd + it * 8;
            CP16(Vsh + (uint32_t)(d * VSTR + vc4) * 4,
                 gvp_base + (size_t)d * SKk + vc4);
        }
        CP_COMMIT();
    }

    float oacc[4][4];
#pragma unroll
    for (int j = 0; j < 4; j++)
#pragma unroll
        for (int t = 0; t < 4; t++) oacc[j][t] = 0.f;

    float m_run = -1e30f, l_run = 0.f;

    for (int cidx = 0; cidx < 16; cidx++) {
        const int jc = cidx * 64;
        const uint32_t* Vu = (const uint32_t*)(Vbase + (cidx & 1) * 64 * VSTR);

        CP_WAIT0();
        __syncthreads();

        if (cidx + 1 < 16) {
            uint32_t vdst = Vsh + (uint32_t)(((cidx + 1) & 1) * 64 * VSTR) * 4;
            const float* vsrc = gvp_base + (cidx + 1) * 64;
#pragma unroll
            for (int it = 0; it < 8; it++) {
                int d = vd + it * 8;
                CP16(vdst + (uint32_t)(d * VSTR + vc4) * 4,
                     vsrc + (size_t)d * SKk + vc4);
            }
            CP_COMMIT();
        }

        float sacc[5][4], pacc[4][4];
#pragma unroll
        for (int j = 0; j < 5; j++)
#pragma unroll
            for (int t = 0; t < 4; t++) sacc[j][t] = 0.f;
#pragma unroll
        for (int j = 0; j < 4; j++)
#pragma unroll
            for (int t = 0; t < 4; t++) pacc[j][t] = 0.f;

#pragma unroll
        for (int k0 = 0; k0 < 64; k0 += 8) {
            int ar = (m0 + gid) * QSTR + k0 + tig;
            uint32_t a0 = Qu[ar];
            uint32_t a1 = Qu[ar + 8 * QSTR];
            uint32_t a2 = Qu[ar + 4];
            uint32_t a3 = Qu[ar + 8 * QSTR + 4];
#pragma unroll
            for (int jj = 0; jj < 5; jj++) {
                int br = ((jt0 + jj) * 8 + gid) * KSTR + k0 + tig;
                MMA_TF32(sacc[jj], a0, a1, a2, a3, Ku[br], Ku[br + 4]);
            }
#pragma unroll
            for (int j = 0; j < 4; j++) {
                int br = (np0 + 8 * j + gid) * QSTR + k0 + tig;
                MMA_TF32(pacc[j], a0, a1, a2, a3, PEu[br], PEu[br + 4]);
            }
        }

#pragma unroll
        for (int jj = 0; jj < 5; jj++) {
            int col = (jt0 + jj) * 8 + 2 * tig;
            int r0 = m0 + gid, r1 = r0 + 8;
            int t00 = col - r0, t10 = col - r1;
            if ((unsigned)t00 < 64u)       Srel[r0 * QSTR + t00]     = sacc[jj][0];
            if ((unsigned)(t00 + 1) < 64u) Srel[r0 * QSTR + t00 + 1] = sacc[jj][1];
            if ((unsigned)t10 < 64u)       Srel[r1 * QSTR + t10]     = sacc[jj][2];
            if ((unsigned)(t10 + 1) < 64u) Srel[r1 * QSTR + t10 + 1] = sacc[jj][3];
        }
#pragma unroll
        for (int j = 0; j < 4; j++) {
            int col = np0 + 8 * j + 2 * tig;
            Spe[(m0 + gid) * QSTR + col]     = pacc[j][0];
            Spe[(m0 + gid) * QSTR + col + 1] = pacc[j][1];
            Spe[(m0 + gid + 8) * QSTR + col]     = pacc[j][2];
            Spe[(m0 + gid + 8) * QSTR + col + 1] = pacc[j][3];
        }
        __syncthreads();

        if (cidx + 1 < 16) {
            const float* ksrc = gkp_base + (size_t)(cidx + 1) * 64 * Dd;
            const float* psrc = gpe + (size_t)(cidx + 1) * 64 * Dd;
#pragma unroll
            for (int it = 0; it < 8; it++) {
                int r = kr + it * 16;
                CP16(Ksh + (uint32_t)(r * KSTR + kc4) * 4,
                     ksrc + (size_t)r * Dd + kc4);
            }
#pragma unroll
            for (int it = 0; it < 4; it++) {
                int r = kr + it * 16;
                CP16(PEsh + (uint32_t)(r * QSTR + kc4) * 4,
                     psrc + (size_t)r * Dd + kc4);
            }
            CP_COMMIT();
        }

        {
            float s[16];
            float mloc = -1e30f;
#pragma unroll
            for (int e = 0; e < 16; e++) {
                s[e] = Srel[srow * QSTR + tbase + e] + Spe[srow * QSTR + tbase + e];
                mloc = fmaxf(mloc, s[e]);
            }
            mloc = fmaxf(mloc, __shfl_xor_sync(0xFFFFFFFFu, mloc, 1));
            mloc = fmaxf(mloc, __shfl_xor_sync(0xFFFFFFFFu, mloc, 2));
            float m_new = fmaxf(m_run, mloc);
            float corr  = __expf(m_run - m_new);
            l_run *= corr;
            float p[16], psum = 0.f;
#pragma unroll
            for (int e = 0; e < 16; e++) { p[e] = __expf(s[e] - m_new); psum += p[e]; }
            psum += __shfl_xor_sync(0xFFFFFFFFu, psum, 1);
            psum += __shfl_xor_sync(0xFFFFFFFFu, psum, 2);
            l_run += psum;
            m_run = m_new;
            if (tg4 == 0) corr_s[srow] = corr;

#pragma unroll
            for (int e = 0; e < 16; e++) {
                int t = tbase + e;
                float jj = (float)(jc + t);
                float mk = fminf(1.f, fmaxf(0.f, (jj - 1023.f + spanL) * (1.f / 32.f) + 1.f));
                Ps[srow * PSTR2 + srow + t] = to_tf32(p[e] * mk);
            }
        }
        __syncthreads();

        {
            float cA = corr_s[m0 + gid], cB = corr_s[m0 + gid + 8];
#pragma unroll
            for (int j = 0; j < 4; j++) {
                oacc[j][0] *= cA; oacc[j][1] *= cA;
                oacc[j][2] *= cB; oacc[j][3] *= cB;
            }
#pragma unroll
            for (int kk = 0; kk < 10; kk++) {
                int k0 = (2 * mb + kk) * 8;
                int ar = (m0 + gid) * PSTR2 + k0 + tig;
                uint32_t a0 = Pu[ar];
                uint32_t a1 = Pu[ar + 8 * PSTR2];
                uint32_t a2 = Pu[ar + 4];
                uint32_t a3 = Pu[ar + 8 * PSTR2 + 4];
#pragma unroll
                for (int j = 0; j < 4; j++) {
                    int br = (np0 + 8 * j + gid) * VSTR + k0 + tig;
                    MMA_TF32(oacc[j], a0, a1, a2, a3, Vu[br], Vu[br + 4]);
                }
            }
        }
    }

    __syncthreads();
    if (tg4 == 0) linv_s[srow] = 1.f / l_run;
    __syncthreads();

    {
        float lA = linv_s[m0 + gid], lB = linv_s[m0 + gid + 8];
        int b = bk >> 3;
        int r0 = i0 + m0 + gid;
#pragma unroll
        for (int j = 0; j < 4; j++) {
            int col = np0 + 8 * j + 2 * tig;
            float* p0 = g_ctx + ((size_t)(b * Mm + r0) * Kk + kh) * Dd + col;
            float* p1 = g_ctx + ((size_t)(b * Mm + r0 + 8) * Kk + kh) * Dd + col;
            *(float2*)p0 = make_float2(oacc[j][0] * lA, oacc[j][1] * lA);
            *(float2*)p1 = make_float2(oacc[j][2] * lB, oacc[j][3] * lB);
        }
    }
}

// ---------------------------------------------------------------------------
extern "C" void kernel_launch(void* const* d_in, const int* in_sizes, int n_in,
                              void* d_out, int out_size) {
    const float* query = (const float*)d_in[0];
    const float* key   = (const float*)d_in[1];
    const float* value = (const float*)d_in[2];
    const float* pe    = (const float*)d_in[3];
    const float* Wq    = (const float*)d_in[4];
    const float* Wk    = (const float*)d_in[5];
    const float* Wv    = (const float*)d_in[6];
    const float* Wo    = (const float*)d_in[7];
    const float* span  = (const float*)d_in[8];
    float* out = (float*)d_out;

    cudaFuncSetAttribute(attn_mma_kernel,
                         cudaFuncAttributeMaxDynamicSharedMemorySize,
                         ATTN_SMEM_FLOATS * (int)sizeof(float));
    cudaFuncSetAttribute(proj_fused_kernel,
                         cudaFuncAttributeMaxDynamicSharedMemorySize,
                         PROJ_SMEM_FLOATS * (int)sizeof(float));
    cudaFuncSetAttribute(proj_out_kernel,
                         cudaFuncAttributeMaxDynamicSharedMemorySize,
                         OUT_SMEM_FLOATS * (int)sizeof(float));

    w_prep_kernel<<<1024, 256>>>(Wq, Wk, Wv, Wo);

    proj_fused_kernel<<<912, 256, PROJ_SMEM_FLOATS * (int)sizeof(float)>>>(
        query, key, value, pe);

    attn_mma_kernel<<<dim3(Mm / 64, BKC), 256,
                      ATTN_SMEM_FLOATS * (int)sizeof(float)>>>(span);

    proj_out_kernel<<<dim3(Bb * Mm / 64, 4), 256,
                      OUT_SMEM_FLOATS * (int)sizeof(float)>>>(out);
}

// round 16
// speedup vs baseline: 1.0907x; 1.0283x over previous
#include <cuda_runtime.h>
#include <cuda_bf16.h>
#include <cstdint>

// Problem constants
#define Bb   8
#define Mm   512
#define Ll   1024
#define Hh   512
#define Kk   8
#define Dd   64
#define SKk  1536           // M + L
#define BKC  64             // B * K
#define SCALE 0.125f

// Scratch (device globals)
__device__ float gq[(size_t)BKC * Mm * Dd];      // [bk][s][d]
__device__ float gk[(size_t)BKC * SKk * Dd];     // [bk][s][d]
__device__ float gv[(size_t)BKC * Dd * SKk];     // [bk][d][s]  (transposed)
__device__ float gpe[Ll * Dd];                   // [j][d]
__device__ float g_ctx[(size_t)Bb * Mm * Hh];    // [B, M, K, D]
__device__ float gWr[4 * 512 * 512];             // tf32-rounded Wq,Wk,Wv,Wo

__device__ __forceinline__ float to_tf32(float x) {
    uint32_t r;
    asm("cvt.rna.tf32.f32 %0, %1;" : "=r"(r) : "f"(x));
    return __uint_as_float(r);
}
__device__ __forceinline__ uint32_t rna_u(float x) {
    uint32_t r;
    asm("cvt.rna.tf32.f32 %0, %1;" : "=r"(r) : "f"(x));
    return r;
}

#define MMA_TF32(c, a0, a1, a2, a3, b0, b1)                                   \
    asm volatile(                                                             \
        "mma.sync.aligned.m16n8k8.row.col.f32.tf32.tf32.f32 "                 \
        "{%0,%1,%2,%3},{%4,%5,%6,%7},{%8,%9},{%0,%1,%2,%3};"                  \
        : "+f"(c[0]), "+f"(c[1]), "+f"(c[2]), "+f"(c[3])                      \
        : "r"(a0), "r"(a1), "r"(a2), "r"(a3), "r"(b0), "r"(b1));

#define CP16(dst_sh, src)                                                     \
    asm volatile("cp.async.cg.shared.global [%0], [%1], 16;"                  \
                 :: "r"(dst_sh), "l"(src))
#define CP_COMMIT() asm volatile("cp.async.commit_group;")
#define CP_WAIT0()  asm volatile("cp.async.wait_group 0;" ::: "memory")

#define PJSTR 36
#define PJ_BUF (128 * PJSTR)
#define PROJ_SMEM_FLOATS (4 * PJ_BUF)

// ---------------------------------------------------------------------------
// Weight pre-round (rna idempotent -> consumers load raw, bit-identical).
// ---------------------------------------------------------------------------
__global__ void w_prep_kernel(const float* __restrict__ Wq,
                              const float* __restrict__ Wk,
                              const float* __restrict__ Wv,
                              const float* __restrict__ Wo) {
    int idx4 = (blockIdx.x * 256 + threadIdx.x) * 4;
    int plane = idx4 >> 18;
    int off   = idx4 & 262143;
    const float* W = (plane == 0) ? Wq : (plane == 1) ? Wk
                   : (plane == 2) ? Wv : Wo;
    float4 v = *(const float4*)(W + off);
    v.x = to_tf32(v.x); v.y = to_tf32(v.y);
    v.z = to_tf32(v.z); v.w = to_tf32(v.w);
    *(float4*)(gWr + idx4) = v;
}

// ---------------------------------------------------------------------------
// FUSED single-pass tf32 QKV projection + PE prep (R13).
// ---------------------------------------------------------------------------
__global__ __launch_bounds__(256) void proj_fused_kernel(
        const float* __restrict__ query, const float* __restrict__ key,
        const float* __restrict__ value, const float* __restrict__ pe) {
    extern __shared__ float psm[];
    const int bid = blockIdx.x;

    if (bid >= 896) {
        int base = (bid - 896) * 4096 + threadIdx.x;
#pragma unroll
        for (int i = 0; i < 16; i++) {
            int idx = base + i * 256;
            int j = idx >> 6, d = idx & 63;
            gpe[idx] = to_tf32(pe[(size_t)d * Ll + j]);
        }
        return;
    }

    int sel, idx, S;
    const float *X, *W;
    if (bid < 128)      { sel = 0; idx = bid;       X = query; W = gWr;          S = Mm;  }
    else if (bid < 512) { sel = 1; idx = bid - 128; X = key;   W = gWr + 262144; S = SKk; }
    else                { sel = 2; idx = bid - 512; X = value; W = gWr + 524288; S = SKk; }

    const uint32_t base_sh = (uint32_t)__cvta_generic_to_shared(psm);
    const int tid  = threadIdx.x;
    const int lane = tid & 31;
    const int wid  = tid >> 5;
    const int warp_m = wid >> 1;
    const int warp_n = wid & 1;
    const int gid = lane >> 2;
    const int tig = lane & 3;
    const int row0 = (idx >> 2) * 128;
    const int col0 = (idx & 3) * 128;

    float c[2][8][4];
#pragma unroll
    for (int f = 0; f < 2; f++)
#pragma unroll
        for (int j = 0; j < 8; j++)
#pragma unroll
            for (int t = 0; t < 4; t++) c[f][j][t] = 0.f;

#pragma unroll
    for (int i = 0; i < 4; i++) {
        int f4 = tid + i * 256;
        int r  = f4 >> 3;
        int kq = (f4 & 7) << 2;
        CP16(base_sh + (uint32_t)(r * PJSTR + kq) * 4,
             X + (size_t)(row0 + r) * 512 + kq);
        CP16(base_sh + (uint32_t)(2 * PJ_BUF + r * PJSTR + kq) * 4,
             W + (size_t)(col0 + r) * 512 + kq);
    }
    CP_COMMIT();

    for (int kt = 0; kt < 16; kt++) {
        CP_WAIT0();
        __syncthreads();

        if (kt + 1 < 16) {
            int nb = (kt + 1) & 1;
            int k0 = (kt + 1) * 32;
#pragma unroll
            for (int i = 0; i < 4; i++) {
                int f4 = tid + i * 256;
                int r  = f4 >> 3;
                int kq = (f4 & 7) << 2;
                CP16(base_sh + (uint32_t)(nb * PJ_BUF + r * PJSTR + kq) * 4,
                     X + (size_t)(row0 + r) * 512 + k0 + kq);
                CP16(base_sh + (uint32_t)((2 + nb) * PJ_BUF + r * PJSTR + kq) * 4,
                     W + (size_t)(col0 + r) * 512 + k0 + kq);
            }
            CP_COMMIT();
        }

        const float* Xs = psm + (kt & 1) * PJ_BUF;
        const uint32_t* Wsu = (const uint32_t*)(psm + (2 + (kt & 1)) * PJ_BUF);

#pragma unroll
        for (int kk = 0; kk < 32; kk += 8) {
            uint32_t a[2][4];
#pragma unroll
            for (int f = 0; f < 2; f++) {
                int rbase = warp_m * 32 + f * 16 + gid;
#pragma unroll
                for (int rg = 0; rg < 4; rg++) {
                    int r    = rbase + ((rg & 1) << 3);
                    int kcol = kk + tig + ((rg >> 1) << 2);
                    a[f][rg] = rna_u(Xs[r * PJSTR + kcol]);
                }
            }
#pragma unroll
            for (int j = 0; j < 8; j++) {
                int cidx = warp_n * 64 + j * 8 + gid;
                uint32_t b0 = Wsu[cidx * PJSTR + kk + tig];
                uint32_t b1 = Wsu[cidx * PJSTR + kk + tig + 4];
#pragma unroll
                for (int f = 0; f < 2; f++)
                    MMA_TF32(c[f][j], a[f][0], a[f][1], a[f][2], a[f][3], b0, b1);
            }
        }
    }

    if (sel < 2) {
#pragma unroll
        for (int f = 0; f < 2; f++) {
            int rloc = warp_m * 32 + f * 16 + gid;
#pragma unroll
            for (int j = 0; j < 8; j++) {
                int cc = col0 + warp_n * 64 + j * 8 + 2 * tig;
#pragma unroll
                for (int h = 0; h < 2; h++) {
                    int r = row0 + rloc + h * 8;
                    int b = r / S, s = r - b * S;
                    int kh = cc >> 6, d = cc & 63;
                    int bk = b * Kk + kh;
                    float tx = to_tf32(c[f][j][h * 2]);
                    float ty = to_tf32(c[f][j][h * 2 + 1]);
                    if (sel == 0)
                        *(float2*)&gq[((size_t)bk * Mm + s) * Dd + d] = make_float2(tx, ty);
                    else
                        *(float2*)&gk[((size_t)bk * SKk + s) * Dd + d] = make_float2(tx, ty);
                }
            }
        }
    } else {
        __syncthreads();
        float* Ts = psm;
#pragma unroll
        for (int f = 0; f < 2; f++)
#pragma unroll
            for (int j = 0; j < 8; j++)
#pragma unroll
                for (int h = 0; h < 2; h++) {
                    int rl  = warp_m * 32 + f * 16 + gid + h * 8;
                    int ccl = warp_n * 64 + j * 8 + 2 * tig;
                    Ts[ccl * 132 + rl]       = to_tf32(c[f][j][h * 2]);
                    Ts[(ccl + 1) * 132 + rl] = to_tf32(c[f][j][h * 2 + 1]);
                }
        __syncthreads();
        int b     = row0 / SKk;
        int sbase = row0 - b * SKk;
        int ccl   = tid >> 1;
        int half  = (tid & 1) * 64;
        int cc = col0 + ccl;
        int kh = cc >> 6, d = cc & 63;
        float* dst = gv + ((size_t)(b * Kk + kh) * Dd + d) * SKk + sbase + half;
        const float* srcrow = Ts + ccl * 132 + half;
#pragma unroll
        for (int i = 0; i < 16; i++)
            *(float4*)(dst + i * 4) = *(const float4*)(srcrow + i * 4);
    }
}

// ---------------------------------------------------------------------------
// Single-pass tf32 output GEMM, 64x128 tiles (R14).
// ---------------------------------------------------------------------------
#define OJ_XBUF (64 * PJSTR)
#define OJ_WBUF (128 * PJSTR)
#define OUT_SMEM_FLOATS (2 * OJ_XBUF + 2 * OJ_WBUF)

__global__ __launch_bounds__(256) void proj_out_kernel(float* __restrict__ Yout) {
    extern __shared__ float psm[];
    const uint32_t base_sh = (uint32_t)__cvta_generic_to_shared(psm);
    const float* W = gWr + 786432;

    const int tid  = threadIdx.x;
    const int lane = tid & 31;
    const int wid  = tid >> 5;
    const int warp_m = wid & 3;
    const int warp_n = wid >> 2;
    const int gid = lane >> 2;
    const int tig = lane & 3;
    const int row0 = blockIdx.x * 64;
    const int col0 = blockIdx.y * 128;

    float c[8][4];
#pragma unroll
    for (int j = 0; j < 8; j++)
#pragma unroll
        for (int t = 0; t < 4; t++) c[j][t] = 0.f;

#pragma unroll
    for (int i = 0; i < 2; i++) {
        int f4 = tid + i * 256;
        int r  = f4 >> 3;
        int kq = (f4 & 7) << 2;
        CP16(base_sh + (uint32_t)(r * PJSTR + kq) * 4,
             g_ctx + (size_t)(row0 + r) * 512 + kq);
    }
#pragma unroll
    for (int i = 0; i < 4; i++) {
        int f4 = tid + i * 256;
        int r  = f4 >> 3;
        int kq = (f4 & 7) << 2;
        CP16(base_sh + (uint32_t)(2 * OJ_XBUF + r * PJSTR + kq) * 4,
             W + (size_t)(col0 + r) * 512 + kq);
    }
    CP_COMMIT();

    for (int kt = 0; kt < 16; kt++) {
        CP_WAIT0();
        __syncthreads();

        if (kt + 1 < 16) {
            int nb = (kt + 1) & 1;
            int k0 = (kt + 1) * 32;
#pragma unroll
            for (int i = 0; i < 2; i++) {
                int f4 = tid + i * 256;
                int r  = f4 >> 3;
                int kq = (f4 & 7) << 2;
                CP16(base_sh + (uint32_t)(nb * OJ_XBUF + r * PJSTR + kq) * 4,
                     g_ctx + (size_t)(row0 + r) * 512 + k0 + kq);
            }
#pragma unroll
            for (int i = 0; i < 4; i++) {
                int f4 = tid + i * 256;
                int r  = f4 >> 3;
                int kq = (f4 & 7) << 2;
                CP16(base_sh + (uint32_t)(2 * OJ_XBUF + nb * OJ_WBUF + r * PJSTR + kq) * 4,
                     W + (size_t)(col0 + r) * 512 + k0 + kq);
            }
            CP_COMMIT();
        }

        const float* Xs = psm + (kt & 1) * OJ_XBUF;
        const uint32_t* Wsu = (const uint32_t*)(psm + 2 * OJ_XBUF + (kt & 1) * OJ_WBUF);

#pragma unroll
        for (int kk = 0; kk < 32; kk += 8) {
            uint32_t a[4];
            int rbase = warp_m * 16 + gid;
#pragma unroll
            for (int rg = 0; rg < 4; rg++) {
                int r    = rbase + ((rg & 1) << 3);
                int kcol = kk + tig + ((rg >> 1) << 2);
                a[rg] = rna_u(Xs[r * PJSTR + kcol]);
            }
#pragma unroll
            for (int j = 0; j < 8; j++) {
                int cidx = warp_n * 64 + j * 8 + gid;
                uint32_t b0 = Wsu[cidx * PJSTR + kk + tig];
                uint32_t b1 = Wsu[cidx * PJSTR + kk + tig + 4];
                MMA_TF32(c[j], a[0], a[1], a[2], a[3], b0, b1);
            }
        }
    }

#pragma unroll
    for (int j = 0; j < 8; j++) {
        int cc = col0 + warp_n * 64 + j * 8 + 2 * tig;
#pragma unroll
        for (int h = 0; h < 2; h++) {
            int r = row0 + warp_m * 16 + gid + h * 8;
            *(float2*)(Yout + (size_t)r * 512 + cc) =
                make_float2(c[j][h * 2], c[j][h * 2 + 1]);
        }
    }
}

// ---------------------------------------------------------------------------
// Single-pass tf32 MMA banded attention — R13 structure +
//  (1) Q fragments hoisted to registers (loop-invariant)
//  (2) Spe merged into Srel: PE scatter writes, pair bar.sync, QK band +=
// Both bit-identical.
// ---------------------------------------------------------------------------
#define QSTR 68
#define KSTR 68
#define VSTR 132
#define PSTR2 132
#define OFF_Q    0
#define OFF_K    (OFF_Q + 64 * QSTR)
#define OFF_PE   (OFF_K + 128 * KSTR)
#define OFF_V    (OFF_PE + 64 * QSTR)
#define OFF_P    (OFF_V + 2 * 64 * VSTR)
#define OFF_SREL (OFF_P + 64 * PSTR2)
#define OFF_CORR (OFF_SREL + 64 * QSTR)
#define OFF_LINV (OFF_CORR + 64)
#define ATTN_SMEM_FLOATS (OFF_LINV + 64)

__global__ __launch_bounds__(256) void attn_mma_kernel(
        const float* __restrict__ span_val) {
    extern __shared__ float sm[];
    float* Qs    = sm + OFF_Q;
    float* Ks    = sm + OFF_K;
    float* PEs   = sm + OFF_PE;
    float* Vbase = sm + OFF_V;
    float* Ps    = sm + OFF_P;
    float* Srel  = sm + OFF_SREL;
    float* corr_s = sm + OFF_CORR;
    float* linv_s = sm + OFF_LINV;

    const uint32_t* Qu  = (const uint32_t*)Qs;
    const uint32_t* Ku  = (const uint32_t*)Ks;
    const uint32_t* PEu = (const uint32_t*)PEs;
    const uint32_t* Pu  = (const uint32_t*)Ps;

    const int tid  = threadIdx.x;
    const int lane = tid & 31;
    const int wid  = tid >> 5;
    const int gid  = lane >> 2;
    const int tig  = lane & 3;
    const int bk   = blockIdx.y;
    const int i0   = blockIdx.x * 64;
    const int kh   = bk & 7;

    const int mb  = wid & 3;
    const int m0  = mb * 16;
    const int np0 = (wid >> 2) * 32;
    const int jt0 = 2 * mb + 5 * (wid >> 2);

    const int srow = tid >> 2;
    const int tg4  = tid & 3;
    const int tbase = tg4 * 16;
    const float spanL = span_val[kh] * 1024.f;

    const float* gkp_base = gk + ((size_t)bk * SKk + i0) * Dd;
    const float* gvp_base = gv + (size_t)bk * Dd * SKk + i0;

    const int kr  = tid >> 4, kc4 = (tid & 15) << 2;
    const int vd  = tid >> 5, vc4 = (tid & 31) << 2;

    const uint32_t Ksh  = (uint32_t)__cvta_generic_to_shared(Ks);
    const uint32_t PEsh = (uint32_t)__cvta_generic_to_shared(PEs);
    const uint32_t Vsh  = (uint32_t)__cvta_generic_to_shared(Vbase);

    // ---- prologue: stage Q, zero P, prefetch chunk 0
    {
        const float* gqp = gq + ((size_t)bk * Mm + i0) * Dd;
#pragma unroll
        for (int it = 0; it < 4; it++) {
            int idx = tid + it * 256;
            int r = idx >> 4, c4 = (idx & 15) << 2;
            float4 v = *(const float4*)(gqp + (size_t)r * Dd + c4);
            v.x *= SCALE; v.y *= SCALE; v.z *= SCALE; v.w *= SCALE;
            *(float4*)&Qs[r * QSTR + c4] = v;
        }
#pragma unroll
        for (int it = 0; it < 33; it++) {
            int idx = tid + it * 256;
            if (idx < 64 * PSTR2) Ps[idx] = 0.f;
        }
#pragma unroll
        for (int it = 0; it < 8; it++) {
            int r = kr + it * 16;
            CP16(Ksh + (uint32_t)(r * KSTR + kc4) * 4,
                 gkp_base + (size_t)r * Dd + kc4);
        }
#pragma unroll
        for (int it = 0; it < 4; it++) {
            int r = kr + it * 16;
            CP16(PEsh + (uint32_t)(r * QSTR + kc4) * 4,
                 gpe + (size_t)r * Dd + kc4);
        }
#pragma unroll
        for (int it = 0; it < 8; it++) {
            int d = vd + it * 8;
            CP16(Vsh + (uint32_t)(d * VSTR + vc4) * 4,
                 gvp_base + (size_t)d * SKk + vc4);
        }
        CP_COMMIT();
    }
    __syncthreads();     // Q smem visible

    // hoist loop-invariant Q fragments to registers
    uint32_t qa[8][4];
#pragma unroll
    for (int kk = 0; kk < 8; kk++) {
        int ar = (m0 + gid) * QSTR + kk * 8 + tig;
        qa[kk][0] = Qu[ar];
        qa[kk][1] = Qu[ar + 8 * QSTR];
        qa[kk][2] = Qu[ar + 4];
        qa[kk][3] = Qu[ar + 8 * QSTR + 4];
    }

    float oacc[4][4];
#pragma unroll
    for (int j = 0; j < 4; j++)
#pragma unroll
        for (int t = 0; t < 4; t++) oacc[j][t] = 0.f;

    float m_run = -1e30f, l_run = 0.f;

    for (int cidx = 0; cidx < 16; cidx++) {
        const int jc = cidx * 64;
        const uint32_t* Vu = (const uint32_t*)(Vbase + (cidx & 1) * 64 * VSTR);

        CP_WAIT0();
        __syncthreads();                 // S1

        if (cidx + 1 < 16) {
            uint32_t vdst = Vsh + (uint32_t)(((cidx + 1) & 1) * 64 * VSTR) * 4;
            const float* vsrc = gvp_base + (cidx + 1) * 64;
#pragma unroll
            for (int it = 0; it < 8; it++) {
                int d = vd + it * 8;
                CP16(vdst + (uint32_t)(d * VSTR + vc4) * 4,
                     vsrc + (size_t)d * SKk + vc4);
            }
            CP_COMMIT();
        }

        // ---- score MMAs (Q frags from registers)
        float sacc[5][4], pacc[4][4];
#pragma unroll
        for (int j = 0; j < 5; j++)
#pragma unroll
            for (int t = 0; t < 4; t++) sacc[j][t] = 0.f;
#pragma unroll
        for (int j = 0; j < 4; j++)
#pragma unroll
            for (int t = 0; t < 4; t++) pacc[j][t] = 0.f;

#pragma unroll
        for (int kk = 0; kk < 8; kk++) {
            int k0 = kk * 8;
            uint32_t a0 = qa[kk][0], a1 = qa[kk][1];
            uint32_t a2 = qa[kk][2], a3 = qa[kk][3];
#pragma unroll
            for (int jj = 0; jj < 5; jj++) {
                int br = ((jt0 + jj) * 8 + gid) * KSTR + k0 + tig;
                MMA_TF32(sacc[jj], a0, a1, a2, a3, Ku[br], Ku[br + 4]);
            }
#pragma unroll
            for (int j = 0; j < 4; j++) {
                int br = (np0 + 8 * j + gid) * QSTR + k0 + tig;
                MMA_TF32(pacc[j], a0, a1, a2, a3, PEu[br], PEu[br + 4]);
            }
        }

        // phase 1: PE scores -> Srel (unique owner per element, full coverage)
#pragma unroll
        for (int j = 0; j < 4; j++) {
            int col = np0 + 8 * j + 2 * tig;
            Srel[(m0 + gid) * QSTR + col]     = pacc[j][0];
            Srel[(m0 + gid) * QSTR + col + 1] = pacc[j][1];
            Srel[(m0 + gid + 8) * QSTR + col]     = pacc[j][2];
            Srel[(m0 + gid + 8) * QSTR + col + 1] = pacc[j][3];
        }
        // pair barrier: both writers of row-block mb (wid = mb and mb+4)
        asm volatile("bar.sync %0, 64;" :: "r"(mb + 1) : "memory");

        // phase 2: de-skewed QK band += (same addends, same order as before)
#pragma unroll
        for (int jj = 0; jj < 5; jj++) {
            int col = (jt0 + jj) * 8 + 2 * tig;
            int r0 = m0 + gid, r1 = r0 + 8;
            int t00 = col - r0, t10 = col - r1;
            if ((unsigned)t00 < 64u)       Srel[r0 * QSTR + t00]     += sacc[jj][0];
            if ((unsigned)(t00 + 1) < 64u) Srel[r0 * QSTR + t00 + 1] += sacc[jj][1];
            if ((unsigned)t10 < 64u)       Srel[r1 * QSTR + t10]     += sacc[jj][2];
            if ((unsigned)(t10 + 1) < 64u) Srel[r1 * QSTR + t10 + 1] += sacc[jj][3];
        }
        __syncthreads();                 // S2: Srel complete; K/PE free

        if (cidx + 1 < 16) {
            const float* ksrc = gkp_base + (size_t)(cidx + 1) * 64 * Dd;
            const float* psrc = gpe + (size_t)(cidx + 1) * 64 * Dd;
#pragma unroll
            for (int it = 0; it < 8; it++) {
                int r = kr + it * 16;
                CP16(Ksh + (uint32_t)(r * KSTR + kc4) * 4,
                     ksrc + (size_t)r * Dd + kc4);
            }
#pragma unroll
            for (int it = 0; it < 4; it++) {
                int r = kr + it * 16;
                CP16(PEsh + (uint32_t)(r * QSTR + kc4) * 4,
                     psrc + (size_t)r * Dd + kc4);
            }
            CP_COMMIT();
        }

        // ---- online softmax (single Srel read)
        {
            float s[16];
            float mloc = -1e30f;
#pragma unroll
            for (int e = 0; e < 16; e++) {
                s[e] = Srel[srow * QSTR + tbase + e];
                mloc = fmaxf(mloc, s[e]);
            }
            mloc = fmaxf(mloc, __shfl_xor_sync(0xFFFFFFFFu, mloc, 1));
            mloc = fmaxf(mloc, __shfl_xor_sync(0xFFFFFFFFu, mloc, 2));
            float m_new = fmaxf(m_run, mloc);
            float corr  = __expf(m_run - m_new);
            l_run *= corr;
            float p[16], psum = 0.f;
#pragma unroll
            for (int e = 0; e < 16; e++) { p[e] = __expf(s[e] - m_new); psum += p[e]; }
            psum += __shfl_xor_sync(0xFFFFFFFFu, psum, 1);
            psum += __shfl_xor_sync(0xFFFFFFFFu, psum, 2);
            l_run += psum;
            m_run = m_new;
            if (tg4 == 0) corr_s[srow] = corr;

#pragma unroll
            for (int e = 0; e < 16; e++) {
                int t = tbase + e;
                float jj = (float)(jc + t);
                float mk = fminf(1.f, fmaxf(0.f, (jj - 1023.f + spanL) * (1.f / 32.f) + 1.f));
                Ps[srow * PSTR2 + srow + t] = to_tf32(p[e] * mk);
            }
        }
        __syncthreads();                 // S3: P ready

        // ---- AV: oacc = oacc*corr + P @ V^T (band k-blocks)
        {
            float cA = corr_s[m0 + gid], cB = corr_s[m0 + gid + 8];
#pragma unroll
            for (int j = 0; j < 4; j++) {
                oacc[j][0] *= cA; oacc[j][1] *= cA;
                oacc[j][2] *= cB; oacc[j][3] *= cB;
            }
#pragma unroll
            for (int kk = 0; kk < 10; kk++) {
                int k0 = (2 * mb + kk) * 8;
                int ar = (m0 + gid) * PSTR2 + k0 + tig;
                uint32_t a0 = Pu[ar];
                uint32_t a1 = Pu[ar + 8 * PSTR2];
                uint32_t a2 = Pu[ar + 4];
                uint32_t a3 = Pu[ar + 8 * PSTR2 + 4];
#pragma unroll
                for (int j = 0; j < 4; j++) {
                    int br = (np0 + 8 * j + gid) * VSTR + k0 + tig;
                    MMA_TF32(oacc[j], a0, a1, a2, a3, Vu[br], Vu[br + 4]);
                }
            }
        }
    }

    __syncthreads();
    if (tg4 == 0) linv_s[srow] = 1.f / l_run;
    __syncthreads();

    // epilogue
    {
        float lA = linv_s[m0 + gid], lB = linv_s[m0 + gid + 8];
        int b = bk >> 3;
        int r0 = i0 + m0 + gid;
#pragma unroll
        for (int j = 0; j < 4; j++) {
            int col = np0 + 8 * j + 2 * tig;
            float* p0 = g_ctx + ((size_t)(b * Mm + r0) * Kk + kh) * Dd + col;
            float* p1 = g_ctx + ((size_t)(b * Mm + r0 + 8) * Kk + kh) * Dd + col;
            *(float2*)p0 = make_float2(oacc[j][0] * lA, oacc[j][1] * lA);
            *(float2*)p1 = make_float2(oacc[j][2] * lB, oacc[j][3] * lB);
        }
    }
}

// ---------------------------------------------------------------------------
extern "C" void kernel_launch(void* const* d_in, const int* in_sizes, int n_in,
                              void* d_out, int out_size) {
    const float* query = (const float*)d_in[0];
    const float* key   = (const float*)d_in[1];
    const float* value = (const float*)d_in[2];
    const float* pe    = (const float*)d_in[3];
    const float* Wq    = (const float*)d_in[4];
    const float* Wk    = (const float*)d_in[5];
    const float* Wv    = (const float*)d_in[6];
    const float* Wo    = (const float*)d_in[7];
    const float* span  = (const float*)d_in[8];
    float* out = (float*)d_out;

    cudaFuncSetAttribute(attn_mma_kernel,
                         cudaFuncAttributeMaxDynamicSharedMemorySize,
                         ATTN_SMEM_FLOATS * (int)sizeof(float));
    cudaFuncSetAttribute(proj_fused_kernel,
                         cudaFuncAttributeMaxDynamicSharedMemorySize,
                         PROJ_SMEM_FLOATS * (int)sizeof(float));
    cudaFuncSetAttribute(proj_out_kernel,
                         cudaFuncAttributeMaxDynamicSharedMemorySize,
                         OUT_SMEM_FLOATS * (int)sizeof(float));

    w_prep_kernel<<<1024, 256>>>(Wq, Wk, Wv, Wo);

    proj_fused_kernel<<<912, 256, PROJ_SMEM_FLOATS * (int)sizeof(float)>>>(
        query, key, value, pe);

    attn_mma_kernel<<<dim3(Mm / 64, BKC), 256,
                      ATTN_SMEM_FLOATS * (int)sizeof(float)>>>(span);

    proj_out_kernel<<<dim3(Bb * Mm / 64, 4), 256,
                      OUT_SMEM_FLOATS * (int)sizeof(float)>>>(out);
}